// round 4
// baseline (speedup 1.0000x reference)
#include <cuda_runtime.h>

// Problem constants
#define S_LEN   64
#define NBATCH  64
#define EMBD    512
#define HIDD    512
#define NVOCAB  10000
#define SB      4096            // S_LEN * NBATCH
#define LOGITS_SZ 40960000      // SB * NVOCAB
#define HFIN_SZ   65536         // 2 * NBATCH * HIDD

#define RCTAS   64              // CTAs per persistent recurrence layer

// Scratch (device globals: no cudaMalloc allowed)
__device__ float g_A0[SB * HIDD];
__device__ float g_H0[SB * HIDD];
__device__ float g_A1[SB * HIDD];
__device__ float g_H1[SB * HIDD];
__device__ int   g_ctr[2 * S_LEN];

// ---------------------------------------------------------------------------
// Generic NT SGEMM:  C[M,N] = A(M,K) * B(N,K)^T + bias1[N] (+ bias2[N])
// A rows optionally gathered through tok[] (embedding lookup).
// Tiling: 128x128 per CTA, BK=16, 256 threads, 8x8 microtile.
// ---------------------------------------------------------------------------
template <bool GATHER>
__global__ __launch_bounds__(256)
void sgemm_nt(const float* __restrict__ A, const int* __restrict__ tok,
              const float* __restrict__ B,
              const float* __restrict__ bias1, const float* __restrict__ bias2,
              float* __restrict__ C, int N, int K, int ldc)
{
    __shared__ float As[16 * 128];
    __shared__ float Bs[16 * 128];

    const int tid = threadIdx.x;
    const int m0  = blockIdx.y * 128;
    const int n0  = blockIdx.x * 128;
    const int tx  = tid & 15;
    const int ty  = tid >> 4;

    const int row0 = tid >> 2;          // 0..63
    const int row1 = row0 + 64;         // 64..127
    const int kq   = (tid & 3) << 2;    // 0,4,8,12

    float4 aR0, aR1, bR0, bR1;

#define LOAD_TILES(K0_)                                                          \
    do {                                                                         \
        const float* pa0 = GATHER ? (A + (size_t)tok[m0 + row0] * K)             \
                                  : (A + (size_t)(m0 + row0) * K);               \
        const float* pa1 = GATHER ? (A + (size_t)tok[m0 + row1] * K)             \
                                  : (A + (size_t)(m0 + row1) * K);               \
        aR0 = *(const float4*)(pa0 + (K0_) + kq);                                \
        aR1 = *(const float4*)(pa1 + (K0_) + kq);                                \
        int gc0 = n0 + row0, gc1 = n0 + row1;                                    \
        bR0 = (gc0 < N) ? *(const float4*)(B + (size_t)gc0 * K + (K0_) + kq)     \
                        : make_float4(0.f, 0.f, 0.f, 0.f);                       \
        bR1 = (gc1 < N) ? *(const float4*)(B + (size_t)gc1 * K + (K0_) + kq)     \
                        : make_float4(0.f, 0.f, 0.f, 0.f);                       \
    } while (0)

    float acc[8][8];
#pragma unroll
    for (int i = 0; i < 8; ++i)
#pragma unroll
        for (int j = 0; j < 8; ++j) acc[i][j] = 0.f;

    LOAD_TILES(0);

    for (int k0 = 0; k0 < K; k0 += 16) {
        {
            int ph = ((row0 >> 2) ^ (kq >> 2));
            int b  = kq * 128 + (ph << 2) + (row0 & 3);
            As[b] = aR0.x; As[b + 128] = aR0.y; As[b + 256] = aR0.z; As[b + 384] = aR0.w;
        }
        {
            int ph = ((row1 >> 2) ^ (kq >> 2));
            int b  = kq * 128 + (ph << 2) + (row1 & 3);
            As[b] = aR1.x; As[b + 128] = aR1.y; As[b + 256] = aR1.z; As[b + 384] = aR1.w;
        }
        {
            int ph = ((row0 >> 2) ^ (kq >> 2));
            int b  = kq * 128 + (ph << 2) + (row0 & 3);
            Bs[b] = bR0.x; Bs[b + 128] = bR0.y; Bs[b + 256] = bR0.z; Bs[b + 384] = bR0.w;
        }
        {
            int ph = ((row1 >> 2) ^ (kq >> 2));
            int b  = kq * 128 + (ph << 2) + (row1 & 3);
            Bs[b] = bR1.x; Bs[b + 128] = bR1.y; Bs[b + 256] = bR1.z; Bs[b + 384] = bR1.w;
        }
        __syncthreads();

        int kn = k0 + 16;
        if (kn < K) LOAD_TILES(kn);   // prefetch next chunk into registers

#pragma unroll
        for (int kk = 0; kk < 16; ++kk) {
            const int x = (kk >> 2);
            float4 a0 = *(const float4*)(As + kk * 128 + ((((ty << 1))     ^ x) << 2));
            float4 a1 = *(const float4*)(As + kk * 128 + ((((ty << 1) + 1) ^ x) << 2));
            float4 b0 = *(const float4*)(Bs + kk * 128 + ((((tx << 1))     ^ x) << 2));
            float4 b1 = *(const float4*)(Bs + kk * 128 + ((((tx << 1) + 1) ^ x) << 2));
            float av[8] = {a0.x, a0.y, a0.z, a0.w, a1.x, a1.y, a1.z, a1.w};
            float bv[8] = {b0.x, b0.y, b0.z, b0.w, b1.x, b1.y, b1.z, b1.w};
#pragma unroll
            for (int i = 0; i < 8; ++i)
#pragma unroll
                for (int j = 0; j < 8; ++j)
                    acc[i][j] = fmaf(av[i], bv[j], acc[i][j]);
        }
        __syncthreads();
    }
#undef LOAD_TILES

    float badd[8];
#pragma unroll
    for (int j = 0; j < 8; ++j) {
        int c = n0 + (tx << 3) + j;
        float b = 0.f;
        if (c < N) {
            b = bias1[c];
            if (bias2) b += bias2[c];
        }
        badd[j] = b;
    }

    if (n0 + 128 <= N) {
#pragma unroll
        for (int i = 0; i < 8; ++i) {
            float* crow = C + (size_t)(m0 + (ty << 3) + i) * ldc + n0 + (tx << 3);
            float4 v0 = make_float4(acc[i][0] + badd[0], acc[i][1] + badd[1],
                                    acc[i][2] + badd[2], acc[i][3] + badd[3]);
            float4 v1 = make_float4(acc[i][4] + badd[4], acc[i][5] + badd[5],
                                    acc[i][6] + badd[6], acc[i][7] + badd[7]);
            *(float4*)(crow)     = v0;
            *(float4*)(crow + 4) = v1;
        }
    } else {
#pragma unroll
        for (int i = 0; i < 8; ++i) {
            float* crow = C + (size_t)(m0 + (ty << 3) + i) * ldc;
#pragma unroll
            for (int j = 0; j < 8; ++j) {
                int c = n0 + (tx << 3) + j;
                if (c < N) crow[c] = acc[i][j] + badd[j];
            }
        }
    }
}

// ---------------------------------------------------------------------------
// Persistent recurrence layer:  for s in 0..63:
//     H[s] = tanh( A[s] + Hprev @ U^T ),  Hprev = (s ? H[s-1] : Hinit)
//
// grid = 64 CTAs x 256 threads. CTA b owns output columns [8b, 8b+8).
// Its U slice (8 x 512, stride-516 padded) lives in SMEM for all 64 steps.
// Per step, Hprev is staged in 64-k chunks (stride-68 padded). Each thread
// computes 1 row x 2 cols; the 4 lanes sharing a row broadcast the H read.
// Steps are separated by a counter-based grid barrier (release/acquire).
// Co-residency: 64 CTAs, 34 KB SMEM, 256 thr <= 148 SMs -> all in wave 1.
// ---------------------------------------------------------------------------
#define USTRIDE 516
#define HSTRIDE 68

__global__ __launch_bounds__(256)
void rnn_layer(const float* __restrict__ Hinit,  // [64,512]
               const float* __restrict__ U,      // [512,512]
               const float* __restrict__ Acc,    // [4096,512] pre-biased
               float* __restrict__ Hout,         // [4096,512]
               int* __restrict__ ctr)            // [64]
{
    __shared__ float Us[8 * USTRIDE];     // 16512 B
    __shared__ float Hs[64 * HSTRIDE];    // 17408 B

    const int tid  = threadIdx.x;
    const int n0   = blockIdx.x * 8;
    const int lane = tid & 31;
    const int row  = (tid >> 5) * 8 + (lane >> 2);   // 0..63
    const int cp   = lane & 3;                       // col pair 0..3
    const int c0   = cp * 2;
    const int c1   = c0 + 1;

    // Load U slice once: 8 cols x 512 k
#pragma unroll
    for (int l = 0; l < 4; ++l) {
        int idx = tid + l * 256;            // 0..1023
        int col = idx >> 7;                 // 0..7
        int kq  = (idx & 127) << 2;         // 0..508
        *(float4*)(Us + col * USTRIDE + kq) =
            *(const float4*)(U + (size_t)(n0 + col) * HIDD + kq);
    }
    __syncthreads();

    const float* Hprev = Hinit;

    for (int s = 0; s < S_LEN; ++s) {
        float acc0 = 0.f, acc1 = 0.f;

#pragma unroll 1
        for (int kb = 0; kb < HIDD; kb += 64) {
            // stage H chunk: 64 rows x 64 k
#pragma unroll
            for (int l = 0; l < 4; ++l) {
                int idx = tid + l * 256;        // 0..1023
                int r   = idx >> 4;             // 0..63
                int kq  = (idx & 15) << 2;      // 0..60
                *(float4*)(Hs + r * HSTRIDE + kq) =
                    *(const float4*)(Hprev + (size_t)r * HIDD + kb + kq);
            }
            __syncthreads();

#pragma unroll
            for (int kk = 0; kk < 64; kk += 4) {
                float4 h  = *(const float4*)(Hs + row * HSTRIDE + kk);
                float4 u0 = *(const float4*)(Us + c0 * USTRIDE + kb + kk);
                float4 u1 = *(const float4*)(Us + c1 * USTRIDE + kb + kk);
                acc0 = fmaf(h.x, u0.x, acc0);
                acc0 = fmaf(h.y, u0.y, acc0);
                acc0 = fmaf(h.z, u0.z, acc0);
                acc0 = fmaf(h.w, u0.w, acc0);
                acc1 = fmaf(h.x, u1.x, acc1);
                acc1 = fmaf(h.y, u1.y, acc1);
                acc1 = fmaf(h.z, u1.z, acc1);
                acc1 = fmaf(h.w, u1.w, acc1);
            }
            __syncthreads();
        }

        // epilogue: add pre-biased A, tanh, store
        {
            size_t base = ((size_t)(s * NBATCH + row)) * HIDD + n0;
            float a0 = Acc[base + c0];
            float a1 = Acc[base + c1];
            Hout[base + c0] = tanhf(acc0 + a0);
            Hout[base + c1] = tanhf(acc1 + a1);
        }

        // grid barrier: release writes, count, spin, acquire
        __threadfence();
        __syncthreads();
        if (tid == 0) {
            atomicAdd(&ctr[s], 1);
            while (*(volatile int*)&ctr[s] < RCTAS) { }
            __threadfence();
        }
        __syncthreads();

        Hprev = Hout + (size_t)s * NBATCH * HIDD;
    }
}

__global__ void zero_ctr_kernel(int* __restrict__ ctr)
{
    int i = blockIdx.x * blockDim.x + threadIdx.x;
    if (i < 2 * S_LEN) ctr[i] = 0;
}

__global__ void finalize_kernel(const float* __restrict__ H0,
                                const float* __restrict__ H1,
                                float* __restrict__ out)
{
    int idx = blockIdx.x * blockDim.x + threadIdx.x;   // 0..65535
    float v;
    if (idx < NBATCH * HIDD)
        v = H0[(size_t)(S_LEN - 1) * NBATCH * HIDD + idx];
    else
        v = H1[(size_t)(S_LEN - 1) * NBATCH * HIDD + (idx - NBATCH * HIDD)];
    out[(size_t)LOGITS_SZ + idx] = v;
}

// ---------------------------------------------------------------------------
extern "C" void kernel_launch(void* const* d_in, const int* in_sizes, int n_in,
                              void* d_out, int out_size)
{
    const int*   tok    = (const int*)  d_in[0];
    const float* hidden = (const float*)d_in[1];
    const float* emb    = (const float*)d_in[2];
    const float* W0     = (const float*)d_in[3];
    const float* bW0    = (const float*)d_in[4];
    const float* W1     = (const float*)d_in[5];
    const float* bW1    = (const float*)d_in[6];
    const float* U0     = (const float*)d_in[7];
    const float* bU0    = (const float*)d_in[8];
    const float* U1     = (const float*)d_in[9];
    const float* bU1    = (const float*)d_in[10];
    const float* Wd     = (const float*)d_in[11];
    const float* bd     = (const float*)d_in[12];
    float* out = (float*)d_out;

    float *A0, *H0, *A1, *H1;
    int* ctr;
    cudaGetSymbolAddress((void**)&A0, g_A0);
    cudaGetSymbolAddress((void**)&H0, g_H0);
    cudaGetSymbolAddress((void**)&A1, g_A1);
    cudaGetSymbolAddress((void**)&H1, g_H1);
    cudaGetSymbolAddress((void**)&ctr, g_ctr);

    zero_ctr_kernel<<<1, 128>>>(ctr);

    // A0 = emb[tok] @ W0^T + bW0 + bU0   (M=4096, N=512, K=512)
    sgemm_nt<true><<<dim3(4, 32), 256>>>(emb, tok, W0, bW0, bU0, A0,
                                         HIDD, EMBD, HIDD);

    // layer-0 recurrence (persistent)
    rnn_layer<<<RCTAS, 256>>>(hidden, U0, A0, H0, ctr);

    // A1 = H0 @ W1^T + bW1 + bU1
    sgemm_nt<false><<<dim3(4, 32), 256>>>(H0, nullptr, W1, bW1, bU1, A1,
                                          HIDD, HIDD, HIDD);

    // layer-1 recurrence (persistent)
    rnn_layer<<<RCTAS, 256>>>(hidden + NBATCH * HIDD, U1, A1, H1,
                              ctr + S_LEN);

    // logits = H1 @ Wd^T + bd   (M=4096, N=10000, K=512)
    sgemm_nt<false><<<dim3((NVOCAB + 127) / 128, 32), 256>>>(
        H1, nullptr, Wd, bd, nullptr, out, NVOCAB, HIDD, NVOCAB);

    // h_final
    if (out_size >= LOGITS_SZ + HFIN_SZ)
        finalize_kernel<<<HFIN_SZ / 256, 256>>>(H0, H1, out);
}

// round 5
// speedup vs baseline: 1.0476x; 1.0476x over previous
#include <cuda_runtime.h>

// Problem constants
#define S_LEN   64
#define NBATCH  64
#define EMBD    512
#define HIDD    512
#define NVOCAB  10000
#define SB      4096            // S_LEN * NBATCH
#define LOGITS_SZ 40960000      // SB * NVOCAB
#define HFIN_SZ   65536         // 2 * NBATCH * HIDD

#define RCTAS   64              // CTAs per persistent recurrence layer

// Scratch (device globals: no cudaMalloc allowed)
__device__ float g_A0[SB * HIDD];
__device__ float g_H0[SB * HIDD];
__device__ float g_A1[SB * HIDD];
__device__ float g_H1[SB * HIDD];
__device__ int   g_ctr[2 * S_LEN];

// ---------------------------------------------------------------------------
// Generic NT SGEMM:  C[M,N] = A(M,K) * B(N,K)^T + bias1[N] (+ bias2[N])
// A rows optionally gathered through tok[] (embedding lookup).
// Tiling: 128x128 per CTA, BK=16, 256 threads, 8x8 microtile.
// Double-buffered SMEM: one __syncthreads per k-iteration.
// ---------------------------------------------------------------------------
template <bool GATHER>
__global__ __launch_bounds__(256)
void sgemm_nt(const float* __restrict__ A, const int* __restrict__ tok,
              const float* __restrict__ B,
              const float* __restrict__ bias1, const float* __restrict__ bias2,
              float* __restrict__ C, int N, int K, int ldc)
{
    __shared__ float As[2][16 * 128];
    __shared__ float Bs[2][16 * 128];

    const int tid = threadIdx.x;
    const int m0  = blockIdx.y * 128;
    const int n0  = blockIdx.x * 128;
    const int tx  = tid & 15;
    const int ty  = tid >> 4;

    const int row0 = tid >> 2;          // 0..63
    const int row1 = row0 + 64;         // 64..127
    const int kq   = (tid & 3) << 2;    // 0,4,8,12

    // hoisted row base pointers
    const float* pa0 = GATHER ? (A + (size_t)tok[m0 + row0] * K)
                              : (A + (size_t)(m0 + row0) * K);
    const float* pa1 = GATHER ? (A + (size_t)tok[m0 + row1] * K)
                              : (A + (size_t)(m0 + row1) * K);
    const int gc0 = n0 + row0, gc1 = n0 + row1;
    const float* pb0 = B + (size_t)gc0 * K;
    const float* pb1 = B + (size_t)gc1 * K;
    const bool  v0 = (gc0 < N), v1 = (gc1 < N);

    float4 aR0, aR1, bR0, bR1;

#define LOAD_TILES(K0_)                                                        \
    do {                                                                       \
        aR0 = *(const float4*)(pa0 + (K0_) + kq);                              \
        aR1 = *(const float4*)(pa1 + (K0_) + kq);                              \
        bR0 = v0 ? *(const float4*)(pb0 + (K0_) + kq)                          \
                 : make_float4(0.f, 0.f, 0.f, 0.f);                            \
        bR1 = v1 ? *(const float4*)(pb1 + (K0_) + kq)                          \
                 : make_float4(0.f, 0.f, 0.f, 0.f);                            \
    } while (0)

#define STORE_TILES(BUF_)                                                      \
    do {                                                                       \
        float* Ad = As[BUF_];                                                  \
        float* Bd = Bs[BUF_];                                                  \
        {                                                                      \
            int ph = ((row0 >> 2) ^ (kq >> 2));                                \
            int b  = kq * 128 + (ph << 2) + (row0 & 3);                        \
            Ad[b] = aR0.x; Ad[b + 128] = aR0.y;                                \
            Ad[b + 256] = aR0.z; Ad[b + 384] = aR0.w;                          \
            Bd[b] = bR0.x; Bd[b + 128] = bR0.y;                                \
            Bd[b + 256] = bR0.z; Bd[b + 384] = bR0.w;                          \
        }                                                                      \
        {                                                                      \
            int ph = ((row1 >> 2) ^ (kq >> 2));                                \
            int b  = kq * 128 + (ph << 2) + (row1 & 3);                        \
            Ad[b] = aR1.x; Ad[b + 128] = aR1.y;                                \
            Ad[b + 256] = aR1.z; Ad[b + 384] = aR1.w;                          \
            Bd[b] = bR1.x; Bd[b + 128] = bR1.y;                                \
            Bd[b + 256] = bR1.z; Bd[b + 384] = bR1.w;                          \
        }                                                                      \
    } while (0)

    float acc[8][8];
#pragma unroll
    for (int i = 0; i < 8; ++i)
#pragma unroll
        for (int j = 0; j < 8; ++j) acc[i][j] = 0.f;

    LOAD_TILES(0);
    STORE_TILES(0);
    __syncthreads();

    int buf = 0;
    for (int k0 = 0; k0 < K; k0 += 16) {
        const int kn = k0 + 16;
        if (kn < K) LOAD_TILES(kn);       // prefetch next chunk into regs

        const float* Ac = As[buf];
        const float* Bc = Bs[buf];
#pragma unroll
        for (int kk = 0; kk < 16; ++kk) {
            const int x = (kk >> 2);
            float4 a0 = *(const float4*)(Ac + kk * 128 + ((((ty << 1))     ^ x) << 2));
            float4 a1 = *(const float4*)(Ac + kk * 128 + ((((ty << 1) + 1) ^ x) << 2));
            float4 b0 = *(const float4*)(Bc + kk * 128 + ((((tx << 1))     ^ x) << 2));
            float4 b1 = *(const float4*)(Bc + kk * 128 + ((((tx << 1) + 1) ^ x) << 2));
            float av[8] = {a0.x, a0.y, a0.z, a0.w, a1.x, a1.y, a1.z, a1.w};
            float bv[8] = {b0.x, b0.y, b0.z, b0.w, b1.x, b1.y, b1.z, b1.w};
#pragma unroll
            for (int i = 0; i < 8; ++i)
#pragma unroll
                for (int j = 0; j < 8; ++j)
                    acc[i][j] = fmaf(av[i], bv[j], acc[i][j]);
        }

        if (kn < K) STORE_TILES(buf ^ 1); // fill the other buffer
        __syncthreads();
        buf ^= 1;
    }
#undef LOAD_TILES
#undef STORE_TILES

    // epilogue: bias add + store
    float badd[8];
#pragma unroll
    for (int j = 0; j < 8; ++j) {
        int c = n0 + (tx << 3) + j;
        float b = 0.f;
        if (c < N) {
            b = bias1[c];
            if (bias2) b += bias2[c];
        }
        badd[j] = b;
    }

    if (n0 + 128 <= N) {
#pragma unroll
        for (int i = 0; i < 8; ++i) {
            float* crow = C + (size_t)(m0 + (ty << 3) + i) * ldc + n0 + (tx << 3);
            float4 w0 = make_float4(acc[i][0] + badd[0], acc[i][1] + badd[1],
                                    acc[i][2] + badd[2], acc[i][3] + badd[3]);
            float4 w1 = make_float4(acc[i][4] + badd[4], acc[i][5] + badd[5],
                                    acc[i][6] + badd[6], acc[i][7] + badd[7]);
            *(float4*)(crow)     = w0;
            *(float4*)(crow + 4) = w1;
        }
    } else {
#pragma unroll
        for (int i = 0; i < 8; ++i) {
            float* crow = C + (size_t)(m0 + (ty << 3) + i) * ldc;
#pragma unroll
            for (int j = 0; j < 8; ++j) {
                int c = n0 + (tx << 3) + j;
                if (c < N) crow[c] = acc[i][j] + badd[j];
            }
        }
    }
}

// ---------------------------------------------------------------------------
// Persistent recurrence layer:  for s in 0..63:
//     H[s] = tanh( A[s] + Hprev @ U^T ),  Hprev = (s ? H[s-1] : Hinit)
//
// grid = 64 CTAs x 256 threads. CTA b owns output columns [8b, 8b+8).
// Dynamic SMEM (148.6 KB): U slice (8x512, stride 516) resident for the
// whole layer + FULL Hprev (64x512, stride 516) staged once per step
// -> only 2 __syncthreads per step. Each thread computes 1 row x 2 cols
// with 4 independent accumulator chains for FMA ILP.
// Steps separated by a counter grid barrier (release/acquire + nanosleep
// backoff). 64 CTAs <= 148 SMs at 1 CTA/SM -> all co-resident, no deadlock.
// ---------------------------------------------------------------------------
#define USTRIDE 516
#define HSTRIDE 516
#define RNN_SMEM_BYTES ((8 * USTRIDE + 64 * HSTRIDE) * 4)   // 148608

__global__ __launch_bounds__(256)
void rnn_layer(const float* __restrict__ Hinit,  // [64,512]
               const float* __restrict__ U,      // [512,512]
               const float* __restrict__ Acc,    // [4096,512] pre-biased
               float* __restrict__ Hout,         // [4096,512]
               int* __restrict__ ctr)            // [64]
{
    extern __shared__ float smem[];
    float* Us = smem;                    // 8 x USTRIDE
    float* Hs = smem + 8 * USTRIDE;      // 64 x HSTRIDE

    const int tid  = threadIdx.x;
    const int n0   = blockIdx.x * 8;
    const int lane = tid & 31;
    const int row  = (tid >> 5) * 8 + (lane >> 2);   // 0..63
    const int c0   = (lane & 3) * 2;
    const int c1   = c0 + 1;

    // Load U slice once: 8 cols x 512 k
#pragma unroll
    for (int l = 0; l < 4; ++l) {
        int idx = tid + l * 256;            // 0..1023
        int col = idx >> 7;                 // 0..7
        int kk  = (idx & 127) << 2;         // 0..508
        *(float4*)(Us + col * USTRIDE + kk) =
            *(const float4*)(U + (size_t)(n0 + col) * HIDD + kk);
    }
    __syncthreads();

    const float* Hprev = Hinit;
    const float* u0p = Us + c0 * USTRIDE;
    const float* u1p = Us + c1 * USTRIDE;

    for (int s = 0; s < S_LEN; ++s) {
        // stage FULL Hprev: 64 rows x 512 k = 8192 float4, 32 per thread
#pragma unroll 8
        for (int l = 0; l < 32; ++l) {
            int idx = tid + l * 256;        // 0..8191
            int r   = idx >> 7;             // 0..63
            int kk  = (idx & 127) << 2;     // 0..508
            *(float4*)(Hs + r * HSTRIDE + kk) =
                *(const float4*)(Hprev + (size_t)r * HIDD + kk);
        }
        __syncthreads();

        // 4 independent accumulator chains
        float a00 = 0.f, a01 = 0.f, a10 = 0.f, a11 = 0.f;
        const float* hrow = Hs + row * HSTRIDE;
#pragma unroll 4
        for (int kk = 0; kk < HIDD; kk += 8) {
            float4 h0  = *(const float4*)(hrow + kk);
            float4 h1  = *(const float4*)(hrow + kk + 4);
            float4 u00 = *(const float4*)(u0p + kk);
            float4 u01 = *(const float4*)(u0p + kk + 4);
            float4 u10 = *(const float4*)(u1p + kk);
            float4 u11 = *(const float4*)(u1p + kk + 4);
            a00 = fmaf(h0.x, u00.x, a00);
            a00 = fmaf(h0.y, u00.y, a00);
            a00 = fmaf(h0.z, u00.z, a00);
            a00 = fmaf(h0.w, u00.w, a00);
            a10 = fmaf(h0.x, u10.x, a10);
            a10 = fmaf(h0.y, u10.y, a10);
            a10 = fmaf(h0.z, u10.z, a10);
            a10 = fmaf(h0.w, u10.w, a10);
            a01 = fmaf(h1.x, u01.x, a01);
            a01 = fmaf(h1.y, u01.y, a01);
            a01 = fmaf(h1.z, u01.z, a01);
            a01 = fmaf(h1.w, u01.w, a01);
            a11 = fmaf(h1.x, u11.x, a11);
            a11 = fmaf(h1.y, u11.y, a11);
            a11 = fmaf(h1.z, u11.z, a11);
            a11 = fmaf(h1.w, u11.w, a11);
        }
        float acc0 = a00 + a01;
        float acc1 = a10 + a11;

        // epilogue: add pre-biased A, tanh, store
        {
            size_t base = ((size_t)(s * NBATCH + row)) * HIDD + n0;
            Hout[base + c0] = tanhf(acc0 + Acc[base + c0]);
            Hout[base + c1] = tanhf(acc1 + Acc[base + c1]);
        }

        // grid barrier: release writes, count, spin (backoff), acquire
        __threadfence();
        __syncthreads();
        if (tid == 0) {
            atomicAdd(&ctr[s], 1);
            while (*(volatile int*)&ctr[s] < RCTAS) __nanosleep(64);
            __threadfence();
        }
        __syncthreads();

        Hprev = Hout + (size_t)s * NBATCH * HIDD;
    }
}

__global__ void zero_ctr_kernel(int* __restrict__ ctr)
{
    int i = blockIdx.x * blockDim.x + threadIdx.x;
    if (i < 2 * S_LEN) ctr[i] = 0;
}

__global__ void finalize_kernel(const float* __restrict__ H0,
                                const float* __restrict__ H1,
                                float* __restrict__ out)
{
    int idx = blockIdx.x * blockDim.x + threadIdx.x;   // 0..65535
    float v;
    if (idx < NBATCH * HIDD)
        v = H0[(size_t)(S_LEN - 1) * NBATCH * HIDD + idx];
    else
        v = H1[(size_t)(S_LEN - 1) * NBATCH * HIDD + (idx - NBATCH * HIDD)];
    out[(size_t)LOGITS_SZ + idx] = v;
}

// ---------------------------------------------------------------------------
extern "C" void kernel_launch(void* const* d_in, const int* in_sizes, int n_in,
                              void* d_out, int out_size)
{
    const int*   tok    = (const int*)  d_in[0];
    const float* hidden = (const float*)d_in[1];
    const float* emb    = (const float*)d_in[2];
    const float* W0     = (const float*)d_in[3];
    const float* bW0    = (const float*)d_in[4];
    const float* W1     = (const float*)d_in[5];
    const float* bW1    = (const float*)d_in[6];
    const float* U0     = (const float*)d_in[7];
    const float* bU0    = (const float*)d_in[8];
    const float* U1     = (const float*)d_in[9];
    const float* bU1    = (const float*)d_in[10];
    const float* Wd     = (const float*)d_in[11];
    const float* bd     = (const float*)d_in[12];
    float* out = (float*)d_out;

    float *A0, *H0, *A1, *H1;
    int* ctr;
    cudaGetSymbolAddress((void**)&A0, g_A0);
    cudaGetSymbolAddress((void**)&H0, g_H0);
    cudaGetSymbolAddress((void**)&A1, g_A1);
    cudaGetSymbolAddress((void**)&H1, g_H1);
    cudaGetSymbolAddress((void**)&ctr, g_ctr);

    cudaFuncSetAttribute(rnn_layer,
                         cudaFuncAttributeMaxDynamicSharedMemorySize,
                         RNN_SMEM_BYTES);

    zero_ctr_kernel<<<1, 128>>>(ctr);

    // A0 = emb[tok] @ W0^T + bW0 + bU0   (M=4096, N=512, K=512)
    sgemm_nt<true><<<dim3(4, 32), 256>>>(emb, tok, W0, bW0, bU0, A0,
                                         HIDD, EMBD, HIDD);

    // layer-0 recurrence (persistent)
    rnn_layer<<<RCTAS, 256, RNN_SMEM_BYTES>>>(hidden, U0, A0, H0, ctr);

    // A1 = H0 @ W1^T + bW1 + bU1
    sgemm_nt<false><<<dim3(4, 32), 256>>>(H0, nullptr, W1, bW1, bU1, A1,
                                          HIDD, HIDD, HIDD);

    // layer-1 recurrence (persistent)
    rnn_layer<<<RCTAS, 256, RNN_SMEM_BYTES>>>(hidden + NBATCH * HIDD, U1,
                                              A1, H1, ctr + S_LEN);

    // logits = H1 @ Wd^T + bd   (M=4096, N=10000, K=512)
    sgemm_nt<false><<<dim3((NVOCAB + 127) / 128, 32), 256>>>(
        H1, nullptr, Wd, bd, nullptr, out, NVOCAB, HIDD, NVOCAB);

    // h_final
    if (out_size >= LOGITS_SZ + HFIN_SZ)
        finalize_kernel<<<HFIN_SZ / 256, 256>>>(H0, H1, out);
}

// round 8
// speedup vs baseline: 1.3196x; 1.2596x over previous
#include <cuda_runtime.h>
#include <cuda_bf16.h>
#include <cstdint>

// Problem constants
#define S_LEN   64
#define NBATCH  64
#define EMBD    512
#define HIDD    512
#define NVOCAB  10000
#define SB      4096            // S_LEN * NBATCH
#define LOGITS_SZ 40960000      // SB * NVOCAB
#define HFIN_SZ   65536         // 2 * NBATCH * HIDD

#define RCTAS   64              // CTAs per persistent recurrence layer

// Split-GEMM dims
#define GK      1536            // 3 * HIDD
#define NPAD    10240           // vocab padded to 128-multiple

// Scratch (device globals: no cudaMalloc allowed)
__device__ float g_A0[SB * HIDD];
__device__ float g_H0[SB * HIDD];
__device__ float g_A1[SB * HIDD];
__device__ float g_H1[SB * HIDD];
__device__ int   g_ctr[2 * S_LEN];
__device__ __nv_bfloat16 g_Ahat[SB * GK];       // [Hhi | Hhi | Hlo]
__device__ __nv_bfloat16 g_Bhat[NPAD * GK];     // [Whi | Wlo | Whi]

// Single dynamic-SMEM symbol (rnn_layer)
extern __shared__ __align__(16) char dynsmem[];

static __device__ __forceinline__ uint32_t smem_u32(const void* p) {
    uint32_t a;
    asm("{ .reg .u64 t; cvta.to.shared.u64 t, %1; cvt.u32.u64 %0, t; }"
        : "=r"(a) : "l"(p));
    return a;
}
static __device__ __forceinline__ void ldm_x4(uint32_t& r0, uint32_t& r1,
                                              uint32_t& r2, uint32_t& r3,
                                              uint32_t addr) {
    asm volatile("ldmatrix.sync.aligned.m8n8.x4.shared.b16 {%0,%1,%2,%3}, [%4];"
                 : "=r"(r0), "=r"(r1), "=r"(r2), "=r"(r3) : "r"(addr));
}
static __device__ __forceinline__ void mma_bf16(float4& d,
                                                uint32_t a0, uint32_t a1,
                                                uint32_t a2, uint32_t a3,
                                                uint32_t b0, uint32_t b1) {
    asm volatile("mma.sync.aligned.m16n8k16.row.col.f32.bf16.bf16.f32 "
                 "{%0,%1,%2,%3}, {%4,%5,%6,%7}, {%8,%9}, {%0,%1,%2,%3};"
                 : "+f"(d.x), "+f"(d.y), "+f"(d.z), "+f"(d.w)
                 : "r"(a0), "r"(a1), "r"(a2), "r"(a3), "r"(b0), "r"(b1));
}

// ---------------------------------------------------------------------------
// Generic NT SGEMM (fp32), used for the two small A-precompute GEMMs.
// 128x128 tile, BK=16, 256 threads, 8x8 microtile, double-buffered SMEM.
// ---------------------------------------------------------------------------
template <bool GATHER>
__global__ __launch_bounds__(256)
void sgemm_nt(const float* __restrict__ A, const int* __restrict__ tok,
              const float* __restrict__ B,
              const float* __restrict__ bias1, const float* __restrict__ bias2,
              float* __restrict__ C, int N, int K, int ldc)
{
    __shared__ float As[2][16 * 128];
    __shared__ float Bs[2][16 * 128];

    const int tid = threadIdx.x;
    const int m0  = blockIdx.y * 128;
    const int n0  = blockIdx.x * 128;
    const int tx  = tid & 15;
    const int ty  = tid >> 4;

    const int row0 = tid >> 2;
    const int row1 = row0 + 64;
    const int kq   = (tid & 3) << 2;

    const float* pa0 = GATHER ? (A + (size_t)tok[m0 + row0] * K)
                              : (A + (size_t)(m0 + row0) * K);
    const float* pa1 = GATHER ? (A + (size_t)tok[m0 + row1] * K)
                              : (A + (size_t)(m0 + row1) * K);
    const int gc0 = n0 + row0, gc1 = n0 + row1;
    const float* pb0 = B + (size_t)gc0 * K;
    const float* pb1 = B + (size_t)gc1 * K;
    const bool  v0 = (gc0 < N), v1 = (gc1 < N);

    float4 aR0, aR1, bR0, bR1;

#define LOAD_TILES(K0_)                                                        \
    do {                                                                       \
        aR0 = *(const float4*)(pa0 + (K0_) + kq);                              \
        aR1 = *(const float4*)(pa1 + (K0_) + kq);                              \
        bR0 = v0 ? *(const float4*)(pb0 + (K0_) + kq)                          \
                 : make_float4(0.f, 0.f, 0.f, 0.f);                            \
        bR1 = v1 ? *(const float4*)(pb1 + (K0_) + kq)                          \
                 : make_float4(0.f, 0.f, 0.f, 0.f);                            \
    } while (0)

#define STORE_TILES(BUF_)                                                      \
    do {                                                                       \
        float* Ad = As[BUF_];                                                  \
        float* Bd = Bs[BUF_];                                                  \
        {                                                                      \
            int ph = ((row0 >> 2) ^ (kq >> 2));                                \
            int b  = kq * 128 + (ph << 2) + (row0 & 3);                        \
            Ad[b] = aR0.x; Ad[b + 128] = aR0.y;                                \
            Ad[b + 256] = aR0.z; Ad[b + 384] = aR0.w;                          \
            Bd[b] = bR0.x; Bd[b + 128] = bR0.y;                                \
            Bd[b + 256] = bR0.z; Bd[b + 384] = bR0.w;                          \
        }                                                                      \
        {                                                                      \
            int ph = ((row1 >> 2) ^ (kq >> 2));                                \
            int b  = kq * 128 + (ph << 2) + (row1 & 3);                        \
            Ad[b] = aR1.x; Ad[b + 128] = aR1.y;                                \
            Ad[b + 256] = aR1.z; Ad[b + 384] = aR1.w;                          \
            Bd[b] = bR1.x; Bd[b + 128] = bR1.y;                                \
            Bd[b + 256] = bR1.z; Bd[b + 384] = bR1.w;                          \
        }                                                                      \
    } while (0)

    float acc[8][8];
#pragma unroll
    for (int i = 0; i < 8; ++i)
#pragma unroll
        for (int j = 0; j < 8; ++j) acc[i][j] = 0.f;

    LOAD_TILES(0);
    STORE_TILES(0);
    __syncthreads();

    int buf = 0;
    for (int k0 = 0; k0 < K; k0 += 16) {
        const int kn = k0 + 16;
        if (kn < K) LOAD_TILES(kn);

        const float* Ac = As[buf];
        const float* Bc = Bs[buf];
#pragma unroll
        for (int kk = 0; kk < 16; ++kk) {
            const int x = (kk >> 2);
            float4 a0 = *(const float4*)(Ac + kk * 128 + ((((ty << 1))     ^ x) << 2));
            float4 a1 = *(const float4*)(Ac + kk * 128 + ((((ty << 1) + 1) ^ x) << 2));
            float4 b0 = *(const float4*)(Bc + kk * 128 + ((((tx << 1))     ^ x) << 2));
            float4 b1 = *(const float4*)(Bc + kk * 128 + ((((tx << 1) + 1) ^ x) << 2));
            float av[8] = {a0.x, a0.y, a0.z, a0.w, a1.x, a1.y, a1.z, a1.w};
            float bv[8] = {b0.x, b0.y, b0.z, b0.w, b1.x, b1.y, b1.z, b1.w};
#pragma unroll
            for (int i = 0; i < 8; ++i)
#pragma unroll
                for (int j = 0; j < 8; ++j)
                    acc[i][j] = fmaf(av[i], bv[j], acc[i][j]);
        }

        if (kn < K) STORE_TILES(buf ^ 1);
        __syncthreads();
        buf ^= 1;
    }
#undef LOAD_TILES
#undef STORE_TILES

    float badd[8];
#pragma unroll
    for (int j = 0; j < 8; ++j) {
        int c = n0 + (tx << 3) + j;
        float b = 0.f;
        if (c < N) {
            b = bias1[c];
            if (bias2) b += bias2[c];
        }
        badd[j] = b;
    }

#pragma unroll
    for (int i = 0; i < 8; ++i) {
        float* crow = C + (size_t)(m0 + (ty << 3) + i) * ldc + n0 + (tx << 3);
        float4 w0 = make_float4(acc[i][0] + badd[0], acc[i][1] + badd[1],
                                acc[i][2] + badd[2], acc[i][3] + badd[3]);
        float4 w1 = make_float4(acc[i][4] + badd[4], acc[i][5] + badd[5],
                                acc[i][6] + badd[6], acc[i][7] + badd[7]);
        *(float4*)(crow)     = w0;
        *(float4*)(crow + 4) = w1;
    }
}

// ---------------------------------------------------------------------------
// Persistent recurrence layer (same as R5)
// ---------------------------------------------------------------------------
#define USTRIDE 516
#define HSTRIDE 516
#define RNN_SMEM_BYTES ((8 * USTRIDE + 64 * HSTRIDE) * 4)   // 148608

__global__ __launch_bounds__(256)
void rnn_layer(const float* __restrict__ Hinit,
               const float* __restrict__ U,
               const float* __restrict__ Acc,
               float* __restrict__ Hout,
               int* __restrict__ ctr)
{
    float* smemf = (float*)dynsmem;
    float* Us = smemf;
    float* Hs = smemf + 8 * USTRIDE;

    const int tid  = threadIdx.x;
    const int n0   = blockIdx.x * 8;
    const int lane = tid & 31;
    const int row  = (tid >> 5) * 8 + (lane >> 2);
    const int c0   = (lane & 3) * 2;
    const int c1   = c0 + 1;

#pragma unroll
    for (int l = 0; l < 4; ++l) {
        int idx = tid + l * 256;
        int col = idx >> 7;
        int kk  = (idx & 127) << 2;
        *(float4*)(Us + col * USTRIDE + kk) =
            *(const float4*)(U + (size_t)(n0 + col) * HIDD + kk);
    }
    __syncthreads();

    const float* Hprev = Hinit;
    const float* u0p = Us + c0 * USTRIDE;
    const float* u1p = Us + c1 * USTRIDE;

    for (int s = 0; s < S_LEN; ++s) {
#pragma unroll 8
        for (int l = 0; l < 32; ++l) {
            int idx = tid + l * 256;
            int r   = idx >> 7;
            int kk  = (idx & 127) << 2;
            *(float4*)(Hs + r * HSTRIDE + kk) =
                *(const float4*)(Hprev + (size_t)r * HIDD + kk);
        }
        __syncthreads();

        float a00 = 0.f, a01 = 0.f, a10 = 0.f, a11 = 0.f;
        const float* hrow = Hs + row * HSTRIDE;
#pragma unroll 4
        for (int kk = 0; kk < HIDD; kk += 8) {
            float4 h0  = *(const float4*)(hrow + kk);
            float4 h1  = *(const float4*)(hrow + kk + 4);
            float4 u00 = *(const float4*)(u0p + kk);
            float4 u01 = *(const float4*)(u0p + kk + 4);
            float4 u10 = *(const float4*)(u1p + kk);
            float4 u11 = *(const float4*)(u1p + kk + 4);
            a00 = fmaf(h0.x, u00.x, a00); a00 = fmaf(h0.y, u00.y, a00);
            a00 = fmaf(h0.z, u00.z, a00); a00 = fmaf(h0.w, u00.w, a00);
            a10 = fmaf(h0.x, u10.x, a10); a10 = fmaf(h0.y, u10.y, a10);
            a10 = fmaf(h0.z, u10.z, a10); a10 = fmaf(h0.w, u10.w, a10);
            a01 = fmaf(h1.x, u01.x, a01); a01 = fmaf(h1.y, u01.y, a01);
            a01 = fmaf(h1.z, u01.z, a01); a01 = fmaf(h1.w, u01.w, a01);
            a11 = fmaf(h1.x, u11.x, a11); a11 = fmaf(h1.y, u11.y, a11);
            a11 = fmaf(h1.z, u11.z, a11); a11 = fmaf(h1.w, u11.w, a11);
        }
        float acc0 = a00 + a01;
        float acc1 = a10 + a11;

        {
            size_t base = ((size_t)(s * NBATCH + row)) * HIDD + n0;
            Hout[base + c0] = tanhf(acc0 + Acc[base + c0]);
            Hout[base + c1] = tanhf(acc1 + Acc[base + c1]);
        }

        __threadfence();
        __syncthreads();
        if (tid == 0) {
            atomicAdd(&ctr[s], 1);
            while (*(volatile int*)&ctr[s] < RCTAS) __nanosleep(64);
            __threadfence();
        }
        __syncthreads();

        Hprev = Hout + (size_t)s * NBATCH * HIDD;
    }
}

// ---------------------------------------------------------------------------
// Split conversions for the bf16 logits GEMM
// ---------------------------------------------------------------------------
__global__ void split_w_kernel(const float* __restrict__ Wd,
                               __nv_bfloat16* __restrict__ Bhat)
{
    for (int idx = blockIdx.x * blockDim.x + threadIdx.x;
         idx < NPAD * HIDD; idx += gridDim.x * blockDim.x) {
        int n = idx >> 9, k = idx & 511;
        float x = (n < NVOCAB) ? Wd[(size_t)n * HIDD + k] : 0.f;
        __nv_bfloat16 hi = __float2bfloat16(x);
        __nv_bfloat16 lo = __float2bfloat16(x - __bfloat162float(hi));
        size_t base = (size_t)n * GK + k;
        Bhat[base]        = hi;
        Bhat[base + 512]  = lo;
        Bhat[base + 1024] = hi;
    }
}

__global__ void split_h_kernel(const float* __restrict__ H1,
                               __nv_bfloat16* __restrict__ Ahat)
{
    for (int idx = blockIdx.x * blockDim.x + threadIdx.x;
         idx < SB * HIDD; idx += gridDim.x * blockDim.x) {
        int m = idx >> 9, k = idx & 511;
        float x = H1[idx];
        __nv_bfloat16 hi = __float2bfloat16(x);
        __nv_bfloat16 lo = __float2bfloat16(x - __bfloat162float(hi));
        size_t base = (size_t)m * GK + k;
        Ahat[base]        = hi;
        Ahat[base + 512]  = hi;
        Ahat[base + 1024] = lo;
    }
}

// ---------------------------------------------------------------------------
// mma.sync (HMMA bf16) logits GEMM: out[4096, 10000] = Ahat @ Bhat^T + bd
// CTA 128x128, BK=32, 8 warps (2m x 4n), warp tile 64x32
// (4 m16 frags x 4 n8 frags), ldmatrix from stride-40 padded SMEM,
// double-buffered with register prefetch. 48 k-iterations.
// ---------------------------------------------------------------------------
#define BM 128
#define BN 128
#define BK 32
#define ASTR 40                 // bf16 units per SMEM row (80 B): conflict-free

__global__ __launch_bounds__(256)
void mma_logits(const __nv_bfloat16* __restrict__ Ahat,
                const __nv_bfloat16* __restrict__ Bhat,
                const float* __restrict__ bd,
                float* __restrict__ out)
{
    __shared__ __nv_bfloat16 As[2][BM * ASTR];
    __shared__ __nv_bfloat16 Bs[2][BN * ASTR];

    const int tid  = threadIdx.x;
    const int wid  = tid >> 5;
    const int lane = tid & 31;
    const int n0   = blockIdx.x * BN;
    const int m0   = blockIdx.y * BM;
    const int wm   = (wid & 1) * 64;    // warp m offset in tile
    const int wn   = (wid >> 1) * 32;   // warp n offset in tile

    const __nv_bfloat16* pa = Ahat + (size_t)m0 * GK;
    const __nv_bfloat16* pb = Bhat + (size_t)n0 * GK;

    // global load mapping: idx = tid + l*256 (l=0,1): r=idx>>2, kc=(idx&3)*8
    const int lr  = tid >> 2;
    const int lkc = (tid & 3) << 3;

    uint4 aR[2], bR[2];
#define GLOAD(KB_)                                                             \
    do {                                                                       \
        aR[0] = *(const uint4*)(pa + (size_t)lr * GK + (KB_) + lkc);           \
        bR[0] = *(const uint4*)(pb + (size_t)lr * GK + (KB_) + lkc);           \
        aR[1] = *(const uint4*)(pa + (size_t)(lr + 64) * GK + (KB_) + lkc);    \
        bR[1] = *(const uint4*)(pb + (size_t)(lr + 64) * GK + (KB_) + lkc);    \
    } while (0)
#define SSTORE(BUF_)                                                           \
    do {                                                                       \
        *(uint4*)(&As[BUF_][lr * ASTR + lkc])        = aR[0];                  \
        *(uint4*)(&Bs[BUF_][lr * ASTR + lkc])        = bR[0];                  \
        *(uint4*)(&As[BUF_][(lr + 64) * ASTR + lkc]) = aR[1];                  \
        *(uint4*)(&Bs[BUF_][(lr + 64) * ASTR + lkc]) = bR[1];                  \
    } while (0)

    float4 acc[4][4];
#pragma unroll
    for (int i = 0; i < 4; ++i)
#pragma unroll
        for (int j = 0; j < 4; ++j) acc[i][j] = make_float4(0.f, 0.f, 0.f, 0.f);

    // ldmatrix lane addressing (bytes within one buffer)
    // A frag i (m16 x k16): row = wm + i*16 + (lane&15), kcol = (lane>>4)*8
    const uint32_t as0 = smem_u32(&As[0][0]);
    const uint32_t bs0 = smem_u32(&Bs[0][0]);
    uint32_t a_off[4];
#pragma unroll
    for (int i = 0; i < 4; ++i)
        a_off[i] = ((wm + i * 16 + (lane & 15)) * ASTR + ((lane >> 4) << 3)) * 2;
    // B pair jp (2 n8 frags): row = wn + jp*16 + (lane&7) + ((lane>>4)<<3),
    //                         kcol = ((lane>>3)&1)*8
    uint32_t b_off[2];
#pragma unroll
    for (int jp = 0; jp < 2; ++jp)
        b_off[jp] = ((wn + jp * 16 + (lane & 7) + ((lane >> 4) << 3)) * ASTR
                     + (((lane >> 3) & 1) << 3)) * 2;

    GLOAD(0);
    SSTORE(0);
    __syncthreads();

    int buf = 0;
    for (int it = 0; it < GK / BK; ++it) {
        if (it + 1 < GK / BK) GLOAD((it + 1) * BK);

        const uint32_t abase = as0 + buf * (BM * ASTR * 2);
        const uint32_t bbase = bs0 + buf * (BN * ASTR * 2);
#pragma unroll
        for (int ks = 0; ks < 2; ++ks) {
            const uint32_t kb = ks * 32;   // 16 bf16 = 32 bytes
            uint32_t a[4][4], b[2][4];
#pragma unroll
            for (int i = 0; i < 4; ++i)
                ldm_x4(a[i][0], a[i][1], a[i][2], a[i][3], abase + a_off[i] + kb);
#pragma unroll
            for (int jp = 0; jp < 2; ++jp)
                ldm_x4(b[jp][0], b[jp][1], b[jp][2], b[jp][3], bbase + b_off[jp] + kb);
#pragma unroll
            for (int i = 0; i < 4; ++i) {
#pragma unroll
                for (int j = 0; j < 4; ++j) {
                    const uint32_t* bj = &b[j >> 1][(j & 1) << 1];
                    mma_bf16(acc[i][j], a[i][0], a[i][1], a[i][2], a[i][3],
                             bj[0], bj[1]);
                }
            }
        }

        if (it + 1 < GK / BK) SSTORE(buf ^ 1);
        __syncthreads();
        buf ^= 1;
    }
#undef GLOAD
#undef SSTORE

    // Epilogue: fragment layout m16n8: d0,d1 -> row (lane>>2), cols (lane&3)*2+{0,1}
    //           d2,d3 -> row (lane>>2)+8
#pragma unroll
    for (int i = 0; i < 4; ++i) {
        const int r0 = m0 + wm + i * 16 + (lane >> 2);
#pragma unroll
        for (int j = 0; j < 4; ++j) {
            const int col = n0 + wn + j * 8 + ((lane & 3) << 1);
            if (col < NVOCAB) {
                const float b0 = bd[col], b1 = bd[col + 1];
                float2 lo = make_float2(acc[i][j].x + b0, acc[i][j].y + b1);
                float2 hi = make_float2(acc[i][j].z + b0, acc[i][j].w + b1);
                *(float2*)(out + (size_t)r0 * NVOCAB + col)       = lo;
                *(float2*)(out + (size_t)(r0 + 8) * NVOCAB + col) = hi;
            }
        }
    }
}

__global__ void zero_ctr_kernel(int* __restrict__ ctr)
{
    int i = blockIdx.x * blockDim.x + threadIdx.x;
    if (i < 2 * S_LEN) ctr[i] = 0;
}

__global__ void finalize_kernel(const float* __restrict__ H0,
                                const float* __restrict__ H1,
                                float* __restrict__ out)
{
    int idx = blockIdx.x * blockDim.x + threadIdx.x;
    float v;
    if (idx < NBATCH * HIDD)
        v = H0[(size_t)(S_LEN - 1) * NBATCH * HIDD + idx];
    else
        v = H1[(size_t)(S_LEN - 1) * NBATCH * HIDD + (idx - NBATCH * HIDD)];
    out[(size_t)LOGITS_SZ + idx] = v;
}

// ---------------------------------------------------------------------------
extern "C" void kernel_launch(void* const* d_in, const int* in_sizes, int n_in,
                              void* d_out, int out_size)
{
    const int*   tok    = (const int*)  d_in[0];
    const float* hidden = (const float*)d_in[1];
    const float* emb    = (const float*)d_in[2];
    const float* W0     = (const float*)d_in[3];
    const float* bW0    = (const float*)d_in[4];
    const float* W1     = (const float*)d_in[5];
    const float* bW1    = (const float*)d_in[6];
    const float* U0     = (const float*)d_in[7];
    const float* bU0    = (const float*)d_in[8];
    const float* U1     = (const float*)d_in[9];
    const float* bU1    = (const float*)d_in[10];
    const float* Wd     = (const float*)d_in[11];
    const float* bd     = (const float*)d_in[12];
    float* out = (float*)d_out;

    float *A0, *H0, *A1, *H1;
    int* ctr;
    __nv_bfloat16 *Ahat, *Bhat;
    cudaGetSymbolAddress((void**)&A0, g_A0);
    cudaGetSymbolAddress((void**)&H0, g_H0);
    cudaGetSymbolAddress((void**)&A1, g_A1);
    cudaGetSymbolAddress((void**)&H1, g_H1);
    cudaGetSymbolAddress((void**)&ctr, g_ctr);
    cudaGetSymbolAddress((void**)&Ahat, g_Ahat);
    cudaGetSymbolAddress((void**)&Bhat, g_Bhat);

    cudaFuncSetAttribute(rnn_layer,
                         cudaFuncAttributeMaxDynamicSharedMemorySize,
                         RNN_SMEM_BYTES);

    zero_ctr_kernel<<<1, 128>>>(ctr);

    // Weight split for logits (independent of recurrence; launch early)
    split_w_kernel<<<512, 256>>>(Wd, Bhat);

    // A0 = emb[tok] @ W0^T + bW0 + bU0
    sgemm_nt<true><<<dim3(4, 32), 256>>>(emb, tok, W0, bW0, bU0, A0,
                                         HIDD, EMBD, HIDD);

    // layer-0 recurrence (persistent)
    rnn_layer<<<RCTAS, 256, RNN_SMEM_BYTES>>>(hidden, U0, A0, H0, ctr);

    // A1 = H0 @ W1^T + bW1 + bU1
    sgemm_nt<false><<<dim3(4, 32), 256>>>(H0, nullptr, W1, bW1, bU1, A1,
                                          HIDD, HIDD, HIDD);

    // layer-1 recurrence (persistent)
    rnn_layer<<<RCTAS, 256, RNN_SMEM_BYTES>>>(hidden + NBATCH * HIDD, U1,
                                              A1, H1, ctr + S_LEN);

    // H1 split, then tensor-core (mma.sync) logits GEMM
    split_h_kernel<<<512, 256>>>(H1, Ahat);
    mma_logits<<<dim3(NPAD / BN, SB / BM), 256>>>(Ahat, Bhat, bd, out);

    // h_final
    if (out_size >= LOGITS_SZ + HFIN_SZ)
        finalize_kernel<<<HFIN_SZ / 256, 256>>>(H0, H1, out);
}